// round 3
// baseline (speedup 1.0000x reference)
#include <cuda_runtime.h>
#include <cstdint>

// MVRModel: ColBERT-style MaxSim scoring (base sm_100 — NO tcgen05 available,
// the bench compiles via compute_100 -> sm_100, which rejects all sm_100a ops).
//   B=16, Q=32, E=128, N=64 docs/batch, D=512 doc tokens.
//   score[b,n] = sum_q qmask[b,q] * max_d( dmask[b,n,d] ? q[b,q]·doc[b,n,d] : MASK )
//
// Ampere-style path: mma.sync.m16n8k8 tf32, cp.async double-buffered 64-token
// chunks (padded smem, conflict-free LDS/LDSM), ldmatrix for A fragments.
// One CTA per (b,n); 83KB smem -> 2 CTAs/SM so loads of one CTA overlap the
// other's prologue/epilogue. Running per-column max in registers.

#define MASKV (-10000.0f)

static constexpr int BB = 16, QQ = 32, EE = 128, NN = 64, DD = 512;
static constexpr int CH = 64;                 // tokens per chunk
static constexpr int NCH = DD / CH;           // 8 chunks
static constexpr int RS = 132;                // padded row stride (floats)
static constexpr int RSB = RS * 4;            // 528 bytes

static constexpr unsigned OFF_Q  = 0;                         // 32 * 528 = 16896
static constexpr unsigned OFF_B0 = 16896;                     // 64 * 528 = 33792
static constexpr unsigned OFF_B1 = 16896 + 33792;             // 50688
static constexpr unsigned OFF_RED = 50688 + 33792;            // 84480, 128 floats
static constexpr unsigned SMEM_BYTES = 84480 + 512;           // 84992

__device__ __forceinline__ uint32_t cvta_smem(const void* p) {
    uint32_t a;
    asm("{ .reg .u64 t; cvta.to.shared.u64 t, %1; cvt.u32.u64 %0, t; }" : "=r"(a) : "l"(p));
    return a;
}

__device__ __forceinline__ void cp16(uint32_t dst, const void* src) {
    asm volatile("cp.async.cg.shared.global [%0], [%1], 16;" :: "r"(dst), "l"(src) : "memory");
}

// One 64-token chunk (32KB payload): 2048 float4s / 128 threads = 16 each.
__device__ __forceinline__ void load_chunk(uint32_t bufbase, const float4* __restrict__ src,
                                           int tid) {
#pragma unroll
    for (int i = 0; i < 16; i++) {
        int idx = tid + i * 128;          // 0..2047
        int r = idx >> 5;                 // token row 0..63
        int j = idx & 31;                 // float4 col
        cp16(bufbase + (uint32_t)r * RSB + (uint32_t)j * 16u, src + idx);
    }
    asm volatile("cp.async.commit_group;" ::: "memory");
}

__global__ void __launch_bounds__(128)
mvr_maxsim_kernel(const float* __restrict__ qe, const int* __restrict__ qm,
                  const float* __restrict__ de, const int* __restrict__ dm,
                  float* __restrict__ out) {
    extern __shared__ char smem[];
    const uint32_t sb = cvta_smem(smem);
    float* red = (float*)(smem + OFF_RED);

    const int tid = threadIdx.x;
    const int wid = tid >> 5;
    const int lid = tid & 31;
    const int doc = blockIdx.x;           // b*64 + n
    const int b = doc >> 6;

    // ---- Prologue: Q (group 0) + chunks 0,1 (groups 1,2) via cp.async ----
    const float4* qg = (const float4*)(qe + (size_t)b * QQ * EE);
#pragma unroll
    for (int i = 0; i < 8; i++) {
        int idx = tid + i * 128;          // 0..1023
        int q = idx >> 5;
        int j = idx & 31;
        cp16(sb + OFF_Q + (uint32_t)q * RSB + (uint32_t)j * 16u, qg + idx);
    }
    asm volatile("cp.async.commit_group;" ::: "memory");

    const float4* dg = (const float4*)(de + (size_t)doc * DD * EE);
    load_chunk(sb + OFF_B0, dg + 0 * CH * 32, tid);
    load_chunk(sb + OFF_B1, dg + 1 * CH * 32, tid);

    // Per-lane ldmatrix address pieces: warp w owns chunk rows [w*16, w*16+16).
    // Lane L supplies row L%16, byte-col (L/16)*16 (matrices 0/1 = k 0..3, 2/3 = k 4..7).
    const uint32_t a_lane_off =
        (uint32_t)(wid * 16 + (lid & 15)) * RSB + (uint32_t)(lid >> 4) * 16u;
    // B fragment base: b0 = Q[n = nt*8 + lane/4][k = ks*8 + lane%4], b1 at k+4.
    const uint32_t b_lane_off = (uint32_t)(lid >> 2) * RSB + (uint32_t)(lid & 3) * 4u;

    const int trow_lane = (lid >> 2);     // 0..7

    float rmax[4][2];
#pragma unroll
    for (int nt = 0; nt < 4; nt++) { rmax[nt][0] = MASKV; rmax[nt][1] = MASKV; }

#pragma unroll
    for (int c = 0; c < NCH; c++) {
        const uint32_t buf = (c & 1) ? (sb + OFF_B1) : (sb + OFF_B0);

        // doc-mask rows for this warp's m16 tile (prefetch before the wait)
        const int trow = c * CH + wid * 16 + trow_lane;
        const int dok0 = dm[doc * DD + trow];
        const int dok1 = dm[doc * DD + trow + 8];

        if (c < NCH - 1) asm volatile("cp.async.wait_group 1;" ::: "memory");
        else             asm volatile("cp.async.wait_group 0;" ::: "memory");
        __syncthreads();

        float acc[4][4];
#pragma unroll
        for (int nt = 0; nt < 4; nt++)
#pragma unroll
            for (int i = 0; i < 4; i++) acc[nt][i] = 0.0f;

#pragma unroll
        for (int ks = 0; ks < 16; ks++) {
            uint32_t a0, a1, a2, a3;
            asm volatile("ldmatrix.sync.aligned.m8n8.x4.shared.b16 {%0,%1,%2,%3}, [%4];"
                         : "=r"(a0), "=r"(a1), "=r"(a2), "=r"(a3)
                         : "r"(buf + a_lane_off + (uint32_t)ks * 32u));
#pragma unroll
            for (int nt = 0; nt < 4; nt++) {
                uint32_t baddr = sb + OFF_Q + b_lane_off
                               + (uint32_t)nt * (8u * RSB) + (uint32_t)ks * 32u;
                uint32_t b0, b1;
                asm volatile("ld.shared.b32 %0, [%1];" : "=r"(b0) : "r"(baddr));
                asm volatile("ld.shared.b32 %0, [%1];" : "=r"(b1) : "r"(baddr + 16u));
                asm volatile(
                    "mma.sync.aligned.m16n8k8.row.col.f32.tf32.tf32.f32 "
                    "{%0,%1,%2,%3}, {%4,%5,%6,%7}, {%8,%9}, {%0,%1,%2,%3};"
                    : "+f"(acc[nt][0]), "+f"(acc[nt][1]), "+f"(acc[nt][2]), "+f"(acc[nt][3])
                    : "r"(a0), "r"(a1), "r"(a2), "r"(a3), "r"(b0), "r"(b1));
            }
        }

        // mask + running column max.
        // acc[nt]: c0=(r, 2c), c1=(r, 2c+1), c2=(r+8, 2c), c3=(r+8, 2c+1),
        // r = lane>>2 within tile, c = lane&3.
#pragma unroll
        for (int nt = 0; nt < 4; nt++) {
            float v0 = dok0 ? acc[nt][0] : MASKV;
            float v1 = dok0 ? acc[nt][1] : MASKV;
            float v2 = dok1 ? acc[nt][2] : MASKV;
            float v3 = dok1 ? acc[nt][3] : MASKV;
            rmax[nt][0] = fmaxf(rmax[nt][0], fmaxf(v0, v2));
            rmax[nt][1] = fmaxf(rmax[nt][1], fmaxf(v1, v3));
        }

        __syncthreads();                  // all warps done reading buf
        if (c + 2 < NCH) load_chunk(buf, dg + (c + 2) * CH * 32, tid);
    }

    // Reduce rmax over the 8 row-groups (lanes differing in bits 2..4).
#pragma unroll
    for (int nt = 0; nt < 4; nt++)
#pragma unroll
        for (int j = 0; j < 2; j++) {
            float x = rmax[nt][j];
#pragma unroll
            for (int o = 4; o < 32; o <<= 1)
                x = fmaxf(x, __shfl_xor_sync(0xFFFFFFFFu, x, o));
            rmax[nt][j] = x;
        }

    if (lid < 4) {
#pragma unroll
        for (int nt = 0; nt < 4; nt++)
#pragma unroll
            for (int j = 0; j < 2; j++)
                red[wid * 32 + nt * 8 + lid * 2 + j] = rmax[nt][j];
    }
    __syncthreads();

    // Final: per-q max over 4 warps, q-mask, sum over q.
    if (tid < 32) {
        float m = fmaxf(fmaxf(red[tid], red[32 + tid]),
                        fmaxf(red[64 + tid], red[96 + tid]));
        const int qok = qm[b * QQ + tid];
        float contrib = (qok != 0 && m != MASKV) ? m : 0.0f;
#pragma unroll
        for (int o = 16; o; o >>= 1)
            contrib += __shfl_xor_sync(0xFFFFFFFFu, contrib, o);
        if (tid == 0) out[doc] = contrib;
    }
}

extern "C" void kernel_launch(void* const* d_in, const int* in_sizes, int n_in,
                              void* d_out, int out_size) {
    (void)in_sizes; (void)n_in; (void)out_size;
    cudaFuncSetAttribute(mvr_maxsim_kernel,
                         cudaFuncAttributeMaxDynamicSharedMemorySize, SMEM_BYTES);
    mvr_maxsim_kernel<<<BB * NN, 128, SMEM_BYTES>>>(
        (const float*)d_in[0], (const int*)d_in[1],
        (const float*)d_in[2], (const int*)d_in[3],
        (float*)d_out);
}

// round 5
// speedup vs baseline: 1.2844x; 1.2844x over previous
#include <cuda_runtime.h>
#include <cstdint>

// MVRModel MaxSim, base sm_100 (no tcgen05 on this toolchain path).
//   B=16, Q=32, E=128, N=64 docs/batch, D=512 doc tokens.
//   score[b,n] = sum_q qmask[b,q] * max_d( dmask ? q·d : MASK ), MASK-max -> 0.
//
// R5 == R4 design (R4 never ran; container infra flake):
// (1) Q (B-operand) fragments preloaded to registers once — inner loop is
// ldmatrix+cvt+mma only; (2) 3-buffer cp.async pipeline keeps 2 chunks in
// flight during compute; (3) cvt.rna.tf32.f32 rounding on both operands
// (halves tf32 truncation bias; R3 rel_err was 7e-4 of 1e-3 budget).

#define MASKV (-10000.0f)

static constexpr int BB = 16, QQ = 32, EE = 128, NN = 64, DD = 512;
static constexpr int CH = 64;                 // tokens per chunk
static constexpr int NCH = DD / CH;           // 8
static constexpr int RS = 132;                // padded row stride (floats)
static constexpr int RSB = RS * 4;            // 528 B

static constexpr unsigned BUFB   = 64u * RSB;           // 33792 per buffer
static constexpr unsigned OFF_B0 = 0;
static constexpr unsigned OFF_B1 = BUFB;
static constexpr unsigned OFF_B2 = 2 * BUFB;            // also holds Q at prologue
static constexpr unsigned OFF_RED = 3 * BUFB;           // 128 floats
static constexpr unsigned SMEM_BYTES = OFF_RED + 512;   // 101888 -> 2 CTAs/SM

__device__ __forceinline__ uint32_t cvta_smem(const void* p) {
    uint32_t a;
    asm("{ .reg .u64 t; cvta.to.shared.u64 t, %1; cvt.u32.u64 %0, t; }" : "=r"(a) : "l"(p));
    return a;
}

__device__ __forceinline__ void cp16(uint32_t dst, const void* src) {
    asm volatile("cp.async.cg.shared.global [%0], [%1], 16;" :: "r"(dst), "l"(src) : "memory");
}

__device__ __forceinline__ uint32_t to_tf32(float x) {
    uint32_t r;
    asm("cvt.rna.tf32.f32 %0, %1;" : "=r"(r) : "f"(x));
    return r;
}

// One 64-token chunk (32KB payload): 2048 float4s / 128 threads = 16 each.
__device__ __forceinline__ void load_chunk(uint32_t bufbase, const float4* __restrict__ src,
                                           int tid) {
#pragma unroll
    for (int i = 0; i < 16; i++) {
        int idx = tid + i * 128;          // 0..2047
        int r = idx >> 5;                 // token row 0..63
        int j = idx & 31;                 // float4 col
        cp16(bufbase + (uint32_t)r * RSB + (uint32_t)j * 16u, src + idx);
    }
    asm volatile("cp.async.commit_group;" ::: "memory");
}

__global__ void __launch_bounds__(128)
mvr_maxsim_kernel(const float* __restrict__ qe, const int* __restrict__ qm,
                  const float* __restrict__ de, const int* __restrict__ dm,
                  float* __restrict__ out) {
    extern __shared__ char smem[];
    const uint32_t sb = cvta_smem(smem);
    float* red = (float*)(smem + OFF_RED);

    const int tid = threadIdx.x;
    const int wid = tid >> 5;
    const int lid = tid & 31;
    const int doc = blockIdx.x;           // b*64 + n
    const int b = doc >> 6;

    // ---- Prologue ----
    // Group 0: Q (32x128) into buf2 (transient). Groups 1,2: chunks 0,1.
    const float4* qg = (const float4*)(qe + (size_t)b * QQ * EE);
#pragma unroll
    for (int i = 0; i < 8; i++) {
        int idx = tid + i * 128;          // 0..1023
        int q = idx >> 5;
        int j = idx & 31;
        cp16(sb + OFF_B2 + (uint32_t)q * RSB + (uint32_t)j * 16u, qg + idx);
    }
    asm volatile("cp.async.commit_group;" ::: "memory");

    const float4* dg = (const float4*)(de + (size_t)doc * DD * EE);
    load_chunk(sb + OFF_B0, dg + 0 * CH * 32, tid);
    load_chunk(sb + OFF_B1, dg + 1 * CH * 32, tid);

    // Wait Q (group 0) done; chunks 0,1 still pending.
    asm volatile("cp.async.wait_group 2;" ::: "memory");
    __syncthreads();

    // Preload B fragments (loop-invariant): bq[nt][ks][j] = tf32(Q[n][k]),
    // n = nt*8 + lane/4, k = ks*8 + (lane%4) + j*4.
    const float* qsm = (const float*)(smem + OFF_B2);
    uint32_t bq[4][16][2];
    {
        const int n_off = (lid >> 2) * RS;
        const int k0 = (lid & 3);
#pragma unroll
        for (int nt = 0; nt < 4; nt++)
#pragma unroll
            for (int ks = 0; ks < 16; ks++) {
                const float* p = qsm + (nt * 8) * RS + n_off + ks * 8 + k0;
                bq[nt][ks][0] = to_tf32(p[0]);
                bq[nt][ks][1] = to_tf32(p[4]);
            }
    }
    __syncthreads();                      // everyone done reading Q from buf2

    // Group 3: chunk 2 into buf2 (overwrites Q region).
    load_chunk(sb + OFF_B2, dg + 2 * CH * 32, tid);

    // ldmatrix lane address: warp w owns rows [w*16, w*16+16) of the chunk.
    const uint32_t a_lane_off =
        (uint32_t)(wid * 16 + (lid & 15)) * RSB + (uint32_t)(lid >> 4) * 16u;
    const int trow_lane = (lid >> 2);     // 0..7

    float rmax[4][2];
#pragma unroll
    for (int nt = 0; nt < 4; nt++) { rmax[nt][0] = MASKV; rmax[nt][1] = MASKV; }

    const uint32_t bufoff[3] = { OFF_B0, OFF_B1, OFF_B2 };

#pragma unroll
    for (int c = 0; c < NCH; c++) {
        const uint32_t buf = sb + bufoff[c % 3];

        // doc-mask rows for this warp's m16 tile (issue before the wait)
        const int trow = c * CH + wid * 16 + trow_lane;
        const int dok0 = dm[doc * DD + trow];
        const int dok1 = dm[doc * DD + trow + 8];

        // Chunk c = group c+1; latest issued group = min(c+2,7)+1.
        if (c < 6)      asm volatile("cp.async.wait_group 2;" ::: "memory");
        else if (c == 6) asm volatile("cp.async.wait_group 1;" ::: "memory");
        else            asm volatile("cp.async.wait_group 0;" ::: "memory");
        __syncthreads();

        float acc[4][4];
#pragma unroll
        for (int nt = 0; nt < 4; nt++)
#pragma unroll
            for (int i = 0; i < 4; i++) acc[nt][i] = 0.0f;

#pragma unroll
        for (int ks = 0; ks < 16; ks++) {
            uint32_t a0, a1, a2, a3;
            asm volatile("ldmatrix.sync.aligned.m8n8.x4.shared.b16 {%0,%1,%2,%3}, [%4];"
                         : "=r"(a0), "=r"(a1), "=r"(a2), "=r"(a3)
                         : "r"(buf + a_lane_off + (uint32_t)ks * 32u));
            a0 = to_tf32(__uint_as_float(a0));
            a1 = to_tf32(__uint_as_float(a1));
            a2 = to_tf32(__uint_as_float(a2));
            a3 = to_tf32(__uint_as_float(a3));
#pragma unroll
            for (int nt = 0; nt < 4; nt++) {
                asm volatile(
                    "mma.sync.aligned.m16n8k8.row.col.f32.tf32.tf32.f32 "
                    "{%0,%1,%2,%3}, {%4,%5,%6,%7}, {%8,%9}, {%0,%1,%2,%3};"
                    : "+f"(acc[nt][0]), "+f"(acc[nt][1]), "+f"(acc[nt][2]), "+f"(acc[nt][3])
                    : "r"(a0), "r"(a1), "r"(a2), "r"(a3),
                      "r"(bq[nt][ks][0]), "r"(bq[nt][ks][1]));
            }
        }

        // mask + running column max.
        // acc[nt]: c0=(r,2c), c1=(r,2c+1), c2=(r+8,2c), c3=(r+8,2c+1);
        // r = lane>>2, c = lane&3 within the tile.
#pragma unroll
        for (int nt = 0; nt < 4; nt++) {
            float v0 = dok0 ? acc[nt][0] : MASKV;
            float v1 = dok0 ? acc[nt][1] : MASKV;
            float v2 = dok1 ? acc[nt][2] : MASKV;
            float v3 = dok1 ? acc[nt][3] : MASKV;
            rmax[nt][0] = fmaxf(rmax[nt][0], fmaxf(v0, v2));
            rmax[nt][1] = fmaxf(rmax[nt][1], fmaxf(v1, v3));
        }

        __syncthreads();                  // all warps done reading buf
        if (c + 3 < NCH) load_chunk(buf, dg + (c + 3) * CH * 32, tid);
    }

    // Reduce rmax over the 8 row-groups (lanes differing in bits 2..4).
#pragma unroll
    for (int nt = 0; nt < 4; nt++)
#pragma unroll
        for (int j = 0; j < 2; j++) {
            float x = rmax[nt][j];
#pragma unroll
            for (int o = 4; o < 32; o <<= 1)
                x = fmaxf(x, __shfl_xor_sync(0xFFFFFFFFu, x, o));
            rmax[nt][j] = x;
        }

    if (lid < 4) {
#pragma unroll
        for (int nt = 0; nt < 4; nt++)
#pragma unroll
            for (int j = 0; j < 2; j++)
                red[wid * 32 + nt * 8 + lid * 2 + j] = rmax[nt][j];
    }
    __syncthreads();

    // Final: per-q max over 4 warps, q-mask, sum over q.
    if (tid < 32) {
        float m = fmaxf(fmaxf(red[tid], red[32 + tid]),
                        fmaxf(red[64 + tid], red[96 + tid]));
        const int qok = qm[b * QQ + tid];
        float contrib = (qok != 0 && m != MASKV) ? m : 0.0f;
#pragma unroll
        for (int o = 16; o; o >>= 1)
            contrib += __shfl_xor_sync(0xFFFFFFFFu, contrib, o);
        if (tid == 0) out[doc] = contrib;
    }
}

extern "C" void kernel_launch(void* const* d_in, const int* in_sizes, int n_in,
                              void* d_out, int out_size) {
    (void)in_sizes; (void)n_in; (void)out_size;
    cudaFuncSetAttribute(mvr_maxsim_kernel,
                         cudaFuncAttributeMaxDynamicSharedMemorySize, SMEM_BYTES);
    mvr_maxsim_kernel<<<BB * NN, 128, SMEM_BYTES>>>(
        (const float*)d_in[0], (const int*)d_in[1],
        (const float*)d_in[2], (const int*)d_in[3],
        (float*)d_out);
}

// round 8
// speedup vs baseline: 1.2872x; 1.0022x over previous
#include <cuda_runtime.h>
#include <cstdint>

// MVRModel MaxSim, base sm_100 (no tcgen05 on this toolchain path).
//   B=16, Q=32, E=128, N=64 docs/batch, D=512 doc tokens.
//   score[b,n] = sum_q qmask[b,q] * max_d( dmask ? q·d : MASK ), MASK-max -> 0.
//
// R7 == R6 design (R6 never ran; container infra flake):
//  - 32-token chunks (16 chunks), 3 buffers x 16.9KB -> 51KB smem -> 4 CTAs/SM
//    (was 2), wave count 4 -> 2, 16 warps/SM.
//  - warp = (m-tile, n-half): bq register tile halves (64 regs) -> ~110 regs,
//    fits __launch_bounds__(128,4) without spill (R5 hit 255 regs).
//  - 2 chunks per CTA continuously in flight; load bursts every ~400cyc.

#define MASKV (-10000.0f)

static constexpr int BB = 16, QQ = 32, EE = 128, NN = 64, DD = 512;
static constexpr int CH = 32;                 // tokens per chunk
static constexpr int NCH = DD / CH;           // 16
static constexpr int RS = 132;                // padded row stride (floats)
static constexpr int RSB = RS * 4;            // 528 B

static constexpr unsigned BUFB   = 32u * RSB;           // 16896 per buffer
static constexpr unsigned OFF_B0 = 0;
static constexpr unsigned OFF_B1 = BUFB;
static constexpr unsigned OFF_B2 = 2 * BUFB;            // holds Q transiently
static constexpr unsigned OFF_RED = 3 * BUFB;           // 64 floats
static constexpr unsigned SMEM_BYTES = OFF_RED + 256;   // 50944 -> 4 CTAs/SM

__device__ __forceinline__ uint32_t cvta_smem(const void* p) {
    uint32_t a;
    asm("{ .reg .u64 t; cvta.to.shared.u64 t, %1; cvt.u32.u64 %0, t; }" : "=r"(a) : "l"(p));
    return a;
}

__device__ __forceinline__ void cp16(uint32_t dst, const void* src) {
    asm volatile("cp.async.cg.shared.global [%0], [%1], 16;" :: "r"(dst), "l"(src) : "memory");
}

__device__ __forceinline__ uint32_t to_tf32(float x) {
    uint32_t r;
    asm("cvt.rna.tf32.f32 %0, %1;" : "=r"(r) : "f"(x));
    return r;
}

// One 32-token chunk (16KB payload): 1024 float4s / 128 threads = 8 each.
__device__ __forceinline__ void load_chunk(uint32_t bufbase, const float4* __restrict__ src,
                                           int tid) {
#pragma unroll
    for (int i = 0; i < 8; i++) {
        int idx = tid + i * 128;          // 0..1023
        int r = idx >> 5;                 // token row 0..31
        int j = idx & 31;                 // float4 col
        cp16(bufbase + (uint32_t)r * RSB + (uint32_t)j * 16u, src + idx);
    }
    asm volatile("cp.async.commit_group;" ::: "memory");
}

__global__ void __launch_bounds__(128, 4)
mvr_maxsim_kernel(const float* __restrict__ qe, const int* __restrict__ qm,
                  const float* __restrict__ de, const int* __restrict__ dm,
                  float* __restrict__ out) {
    extern __shared__ char smem[];
    const uint32_t sb = cvta_smem(smem);
    float* red = (float*)(smem + OFF_RED);

    const int tid = threadIdx.x;
    const int wid = tid >> 5;
    const int lid = tid & 31;
    const int mt = wid & 1;               // m-tile within chunk (rows mt*16..+16)
    const int nh = wid >> 1;              // n-half (query cols nh*16..+16)
    const int doc = blockIdx.x;           // b*64 + n
    const int b = doc >> 6;

    // ---- Prologue ----
    // Group 0: Q (32x128) into buf2 (transient). Groups 1,2: chunks 0,1.
    const float4* qg = (const float4*)(qe + (size_t)b * QQ * EE);
#pragma unroll
    for (int i = 0; i < 8; i++) {
        int idx = tid + i * 128;          // 0..1023
        int q = idx >> 5;
        int j = idx & 31;
        cp16(sb + OFF_B2 + (uint32_t)q * RSB + (uint32_t)j * 16u, qg + idx);
    }
    asm volatile("cp.async.commit_group;" ::: "memory");

    const float4* dg = (const float4*)(de + (size_t)doc * DD * EE);
    load_chunk(sb + OFF_B0, dg + 0 * CH * 32, tid);
    load_chunk(sb + OFF_B1, dg + 1 * CH * 32, tid);

    // Wait Q (group 0) done; chunks 0,1 still pending.
    asm volatile("cp.async.wait_group 2;" ::: "memory");
    __syncthreads();

    // Preload B fragments (loop-invariant): bq[nt][ks][j] = tf32(Q[n][k]),
    // n = nh*16 + nt*8 + lane/4, k = ks*8 + (lane%4) + j*4.
    const float* qsm = (const float*)(smem + OFF_B2);
    uint32_t bq[2][16][2];
    {
        const float* pbase = qsm + (nh * 16 + (lid >> 2)) * RS + (lid & 3);
#pragma unroll
        for (int nt = 0; nt < 2; nt++)
#pragma unroll
            for (int ks = 0; ks < 16; ks++) {
                const float* p = pbase + (nt * 8) * RS + ks * 8;
                bq[nt][ks][0] = to_tf32(p[0]);
                bq[nt][ks][1] = to_tf32(p[4]);
            }
    }
    __syncthreads();                      // everyone done reading Q from buf2

    // Group 3: chunk 2 into buf2 (overwrites Q region).
    load_chunk(sb + OFF_B2, dg + 2 * CH * 32, tid);

    // ldmatrix lane address: this warp owns chunk rows [mt*16, mt*16+16).
    const uint32_t a_lane_off =
        (uint32_t)(mt * 16 + (lid & 15)) * RSB + (uint32_t)(lid >> 4) * 16u;
    const int trow_lane = (lid >> 2);     // 0..7

    float rmax[2][2];
    rmax[0][0] = MASKV; rmax[0][1] = MASKV; rmax[1][0] = MASKV; rmax[1][1] = MASKV;

    const uint32_t bufoff[3] = { OFF_B0, OFF_B1, OFF_B2 };

#pragma unroll
    for (int c = 0; c < NCH; c++) {
        const uint32_t buf = sb + bufoff[c % 3];

        // doc-mask rows for this warp's m16 tile (issue before the wait)
        const int trow = c * CH + mt * 16 + trow_lane;
        const int dok0 = dm[doc * DD + trow];
        const int dok1 = dm[doc * DD + trow + 8];

        // Chunk c = group c+1; latest issued = chunk min(c+2,15) = group +1.
        if (c < NCH - 2)       asm volatile("cp.async.wait_group 2;" ::: "memory");
        else if (c == NCH - 2) asm volatile("cp.async.wait_group 1;" ::: "memory");
        else                   asm volatile("cp.async.wait_group 0;" ::: "memory");
        __syncthreads();

        float acc[2][4];
#pragma unroll
        for (int nt = 0; nt < 2; nt++)
#pragma unroll
            for (int i = 0; i < 4; i++) acc[nt][i] = 0.0f;

#pragma unroll
        for (int ks = 0; ks < 16; ks++) {
            uint32_t a0, a1, a2, a3;
            asm volatile("ldmatrix.sync.aligned.m8n8.x4.shared.b16 {%0,%1,%2,%3}, [%4];"
                         : "=r"(a0), "=r"(a1), "=r"(a2), "=r"(a3)
                         : "r"(buf + a_lane_off + (uint32_t)ks * 32u));
            a0 = to_tf32(__uint_as_float(a0));
            a1 = to_tf32(__uint_as_float(a1));
            a2 = to_tf32(__uint_as_float(a2));
            a3 = to_tf32(__uint_as_float(a3));
#pragma unroll
            for (int nt = 0; nt < 2; nt++) {
                asm volatile(
                    "mma.sync.aligned.m16n8k8.row.col.f32.tf32.tf32.f32 "
                    "{%0,%1,%2,%3}, {%4,%5,%6,%7}, {%8,%9}, {%0,%1,%2,%3};"
                    : "+f"(acc[nt][0]), "+f"(acc[nt][1]), "+f"(acc[nt][2]), "+f"(acc[nt][3])
                    : "r"(a0), "r"(a1), "r"(a2), "r"(a3),
                      "r"(bq[nt][ks][0]), "r"(bq[nt][ks][1]));
            }
        }

        // mask + running column max.
        // acc[nt]: c0=(r,2c), c1=(r,2c+1), c2=(r+8,2c), c3=(r+8,2c+1);
        // r = lane>>2, c = lane&3 within the tile.
#pragma unroll
        for (int nt = 0; nt < 2; nt++) {
            float v0 = dok0 ? acc[nt][0] : MASKV;
            float v1 = dok0 ? acc[nt][1] : MASKV;
            float v2 = dok1 ? acc[nt][2] : MASKV;
            float v3 = dok1 ? acc[nt][3] : MASKV;
            rmax[nt][0] = fmaxf(rmax[nt][0], fmaxf(v0, v2));
            rmax[nt][1] = fmaxf(rmax[nt][1], fmaxf(v1, v3));
        }

        __syncthreads();                  // all warps done reading buf
        if (c + 3 < NCH) load_chunk(buf, dg + (c + 3) * CH * 32, tid);
    }

    // Reduce rmax over the 8 row-groups (lanes differing in bits 2..4).
#pragma unroll
    for (int nt = 0; nt < 2; nt++)
#pragma unroll
        for (int j = 0; j < 2; j++) {
            float x = rmax[nt][j];
#pragma unroll
            for (int o = 4; o < 32; o <<= 1)
                x = fmaxf(x, __shfl_xor_sync(0xFFFFFFFFu, x, o));
            rmax[nt][j] = x;
        }

    // Warp covers 16 columns: local col = nt*8 + (lane&3)*2 + j.
    if (lid < 4) {
#pragma unroll
        for (int nt = 0; nt < 2; nt++)
#pragma unroll
            for (int j = 0; j < 2; j++)
                red[wid * 16 + nt * 8 + lid * 2 + j] = rmax[nt][j];
    }
    __syncthreads();

    // Final: q-column global = nh*16 + local; combine the two m-tiles
    // (warps h*2 and h*2+1), q-mask, sum over q.
    if (tid < 32) {
        const int h = tid >> 4;           // n-half
        const int i = tid & 15;           // column within half
        float m = fmaxf(red[(h * 2) * 16 + i], red[(h * 2 + 1) * 16 + i]);
        const int qok = qm[b * QQ + tid];
        float contrib = (qok != 0 && m != MASKV) ? m : 0.0f;
#pragma unroll
        for (int o = 16; o; o >>= 1)
            contrib += __shfl_xor_sync(0xFFFFFFFFu, contrib, o);
        if (tid == 0) out[doc] = contrib;
    }
}

extern "C" void kernel_launch(void* const* d_in, const int* in_sizes, int n_in,
                              void* d_out, int out_size) {
    (void)in_sizes; (void)n_in; (void)out_size;
    cudaFuncSetAttribute(mvr_maxsim_kernel,
                         cudaFuncAttributeMaxDynamicSharedMemorySize, SMEM_BYTES);
    mvr_maxsim_kernel<<<BB * NN, 128, SMEM_BYTES>>>(
        (const float*)d_in[0], (const int*)d_in[1],
        (const float*)d_in[2], (const int*)d_in[3],
        (float*)d_out);
}